// round 3
// baseline (speedup 1.0000x reference)
#include <cuda_runtime.h>
#include <math.h>

#define NN 20000
#define NE 320000
#define NG 200
#define FI 75
#define NT 5
#define FO 15
#define PRE 375    // towers*F_IN = 5*75
#define PREP 376   // padded (16B-aligned rows)
#define ABW 752    // dst(0..375 pad) + src(376..751 pad)

// ---------------- scratch (device globals; no cudaMalloc allowed) ----------
__device__ float d_x[NN*FI];            // current node features
__device__ float d_AB[NN*ABW];          // per-node message precomp (dst part | src part)
__device__ float d_Wcat[FI*ABW];        // repacked W_pre (x-side)
__device__ float d_Ctab[100*PREP];      // per-edge-type message term (incl. b_pre)
__device__ float d_aggr[NN*NT*300];     // [N][T][mean|min|max|std]
__device__ float d_y[NN*FI];
__device__ float d_y2[NN*FI];
__device__ int   d_deg[NN];
__device__ float d_amp[NN], d_att[NN];
__device__ int   d_off[NN+1], d_cur[NN];
__device__ int   d_csr_src[NE], d_csr_type[NE];
__device__ float d_bnsum[FI], d_bnsq[FI], d_scale[FI], d_shift[FI];
__device__ float d_logsum;
__device__ float d_pool[NG*FI];

// ---------------- setup kernels -------------------------------------------
__global__ void k_init() {
    int i = blockIdx.x * blockDim.x + threadIdx.x;
    if (i < NN) d_deg[i] = 0;
    if (i < NG * FI) d_pool[i] = 0.f;
    if (i == 0) d_logsum = 0.f;
}

__global__ void k_deg(const int* __restrict__ edge_index) {
    int e = blockIdx.x * blockDim.x + threadIdx.x;
    if (e < NE) atomicAdd(&d_deg[edge_index[NE + e]], 1);
}

// single-block shuffle scan over 20000 degrees -> CSR offsets (+cursor copy)
__global__ void k_scan() {
    __shared__ int wsum[32];
    __shared__ int carry_s;
    int lane = threadIdx.x & 31, warp = threadIdx.x >> 5;
    if (threadIdx.x == 0) carry_s = 0;
    __syncthreads();
    for (int base = 0; base < NN; base += 1024) {
        int i = base + threadIdx.x;
        int v = (i < NN) ? d_deg[i] : 0;
        int x = v;
        #pragma unroll
        for (int off = 1; off < 32; off <<= 1) {
            int t = __shfl_up_sync(0xffffffffu, x, off);
            if (lane >= off) x += t;
        }
        if (lane == 31) wsum[warp] = x;
        __syncthreads();
        if (warp == 0) {
            int w = wsum[lane];
            int y = w;
            #pragma unroll
            for (int off = 1; off < 32; off <<= 1) {
                int t = __shfl_up_sync(0xffffffffu, y, off);
                if (lane >= off) y += t;
            }
            wsum[lane] = y - w;   // exclusive warp base
        }
        __syncthreads();
        int excl = x - v + wsum[warp] + carry_s;
        if (i < NN) { d_off[i] = excl; d_cur[i] = excl; }
        __syncthreads();
        if (threadIdx.x == 1023) carry_s = excl + v;
        __syncthreads();
    }
    if (threadIdx.x == 0) d_off[NN] = carry_s;
}

__global__ void k_scatter(const int* __restrict__ edge_index,
                          const int* __restrict__ eattr) {
    int e = blockIdx.x * blockDim.x + threadIdx.x;
    if (e >= NE) return;
    int dst = edge_index[NE + e];
    int p = atomicAdd(&d_cur[dst], 1);
    d_csr_src[p]  = edge_index[e];
    d_csr_type[p] = eattr[e];
}

__global__ void k_logsum() {
    __shared__ float p[256];
    int i = blockIdx.x * 256 + threadIdx.x;
    float v = (i < NN) ? logf((float)d_deg[i] + 1.f) : 0.f;
    p[threadIdx.x] = v;
    __syncthreads();
    for (int s = 128; s > 0; s >>= 1) {
        if (threadIdx.x < s) p[threadIdx.x] += p[threadIdx.x + s];
        __syncthreads();
    }
    if (threadIdx.x == 0) atomicAdd(&d_logsum, p[0]);
}

__global__ void k_scalers() {
    int i = blockIdx.x * blockDim.x + threadIdx.x;
    if (i >= NN) return;
    float avg = d_logsum / (float)NN;
    int deg = d_deg[i];
    float degc = (deg > 0) ? (float)deg : 1.f;
    float ld = logf(degc + 1.f);
    d_amp[i] = ld / avg;
    d_att[i] = avg / ld;
}

__global__ void k_gather_x(const int* __restrict__ x_idx,
                           const float* __restrict__ node_emb) {
    int i = blockIdx.x * blockDim.x + threadIdx.x;
    if (i >= NN * FI) return;
    int n = i / FI, c = i - n * FI;
    d_x[i] = node_emb[x_idx[n] * FI + c];
}

// ---------------- per-layer kernels ---------------------------------------
// repack W_pre x-side into [75][752]: cols 0..374 = dst coeffs, 376..750 = src, pads 0
__global__ void k_repack(const float* __restrict__ W_pre, int l) {
    int i = blockIdx.x * blockDim.x + threadIdx.x;
    if (i >= FI * ABW) return;
    int c = i / ABW, j = i - c * ABW;
    float v = 0.f;
    if (j < PRE) {
        int t = j / FI, f = j - t * FI;
        v = W_pre[(((size_t)l * NT + t) * 225 + c) * FI + f];
    } else if (j >= PREP && j < PREP + PRE) {
        int jj = j - PREP;
        int t = jj / FI, f = jj - t * FI;
        v = W_pre[(((size_t)l * NT + t) * 225 + FI + c) * FI + f];
    }
    d_Wcat[i] = v;
}

// per-edge-type message term: C[type][t*75+f] = (edge_emb@W_edge+b_edge)@W_pre_e + b_pre
__global__ void k_ctab(const float* __restrict__ edge_emb,
                       const float* __restrict__ W_edge,
                       const float* __restrict__ b_edge,
                       const float* __restrict__ W_pre,
                       const float* __restrict__ b_pre, int l) {
    __shared__ float se[FI];
    int t = blockIdx.x;
    if (threadIdx.x < FI) {
        float a = b_edge[l * FI + threadIdx.x];
        #pragma unroll 10
        for (int c = 0; c < 50; c++)
            a += edge_emb[t * 50 + c] * W_edge[(l * 50 + c) * FI + threadIdx.x];
        se[threadIdx.x] = a;
    }
    __syncthreads();
    int j = threadIdx.x;
    if (j < PRE) {
        int tw = j / FI, f = j - tw * FI;
        float a = b_pre[(l * NT + tw) * FI + f];
        #pragma unroll 15
        for (int c = 0; c < FI; c++)
            a += se[c] * W_pre[(((size_t)l * NT + tw) * 225 + 150 + c) * FI + f];
        d_Ctab[t * PREP + j] = a;
    } else if (j == PRE) {
        d_Ctab[t * PREP + PRE] = 0.f;   // pad
    }
}

// AB = x[NN,75] @ Wcat[75,752]
#define BM 64
#define BN 64
#define BK 25
__global__ void k_gemm_ab() {
    __shared__ float As[BM][BK];
    __shared__ float Bs[BK][BN + 1];
    int row0 = blockIdx.y * BM, col0 = blockIdx.x * BN;
    int tx = threadIdx.x & 15, ty = threadIdx.x >> 4;
    float acc[4][4] = {};
    for (int kt = 0; kt < FI; kt += BK) {
        for (int i = threadIdx.x; i < BM * BK; i += 256) {
            int r = i / BK, k = i - r * BK;
            int gr = row0 + r;
            As[r][k] = (gr < NN) ? d_x[gr * FI + kt + k] : 0.f;
        }
        for (int i = threadIdx.x; i < BK * BN; i += 256) {
            int k = i / BN, c = i - k * BN;
            int gc = col0 + c;
            Bs[k][c] = (gc < ABW) ? d_Wcat[(kt + k) * ABW + gc] : 0.f;
        }
        __syncthreads();
        #pragma unroll
        for (int k = 0; k < BK; k++) {
            float a[4], b[4];
            #pragma unroll
            for (int i = 0; i < 4; i++) a[i] = As[ty * 4 + i][k];
            #pragma unroll
            for (int j = 0; j < 4; j++) b[j] = Bs[k][tx * 4 + j];
            #pragma unroll
            for (int i = 0; i < 4; i++)
                #pragma unroll
                for (int j = 0; j < 4; j++) acc[i][j] += a[i] * b[j];
        }
        __syncthreads();
    }
    for (int i = 0; i < 4; i++) {
        int gr = row0 + ty * 4 + i;
        if (gr >= NN) continue;
        for (int j = 0; j < 4; j++) {
            int gc = col0 + tx * 4 + j;
            if (gc < ABW) d_AB[gr * ABW + gc] = acc[i][j];
        }
    }
}

// multi-aggregator reduction per node. block = node, 96 threads, float4 lanes.
// thread t covers features 4t..4t+3 (t < 94 active; feature 375 is zero pad).
__global__ __launch_bounds__(96) void k_agg() {
    int n = blockIdx.x;
    int t = threadIdx.x;
    int begin = d_off[n], end = d_off[n + 1];
    int deg = end - begin;
    if (t >= 94) return;
    const float4* AB4 = (const float4*)d_AB;
    const float4* C4  = (const float4*)d_Ctab;
    float4 a = AB4[n * (ABW / 4) + t];          // dst part
    float4 s = {0,0,0,0}, q = {0,0,0,0};
    float4 mn = { 3.4e38f, 3.4e38f, 3.4e38f, 3.4e38f};
    float4 mx = {-3.4e38f,-3.4e38f,-3.4e38f,-3.4e38f};
    for (int e = begin; e < end; e++) {
        int src = d_csr_src[e];
        int tpe = d_csr_type[e];
        float4 b = AB4[src * (ABW / 4) + (PREP / 4) + t];   // src part
        float4 c = C4[tpe * (PREP / 4) + t];
        float m0 = a.x + b.x + c.x;
        float m1 = a.y + b.y + c.y;
        float m2 = a.z + b.z + c.z;
        float m3 = a.w + b.w + c.w;
        s.x += m0; q.x += m0*m0; mn.x = fminf(mn.x, m0); mx.x = fmaxf(mx.x, m0);
        s.y += m1; q.y += m1*m1; mn.y = fminf(mn.y, m1); mx.y = fmaxf(mx.y, m1);
        s.z += m2; q.z += m2*m2; mn.z = fminf(mn.z, m2); mx.z = fmaxf(mx.z, m2);
        s.w += m3; q.w += m3*m3; mn.w = fminf(mn.w, m3); mx.w = fmaxf(mx.w, m3);
    }
    float invd = (deg > 0) ? 1.f / (float)deg : 1.f;
    float sa[4] = {s.x, s.y, s.z, s.w};
    float qa[4] = {q.x, q.y, q.z, q.w};
    float mna[4] = {mn.x, mn.y, mn.z, mn.w};
    float mxa[4] = {mx.x, mx.y, mx.z, mx.w};
    #pragma unroll
    for (int k = 0; k < 4; k++) {
        int f = 4 * t + k;
        if (f >= PRE) break;
        float mean = sa[k] * invd;
        float msq  = qa[k] * invd;
        float sd = sqrtf(fmaxf(msq - mean * mean, 0.f) + 1e-5f);
        float lo = (deg > 0) ? mna[k] : 0.f;
        float hi = (deg > 0) ? mxa[k] : 0.f;
        int tw = f / FI, ff = f - tw * FI;
        float* o = &d_aggr[(n * NT + tw) * 300 + ff];
        o[0]   = mean;
        o[75]  = lo;
        o[150] = hi;
        o[225] = sd;
    }
}

// post-MLP per tower: y[n, t*15+f]. scaler folding: self + d1 + amp*d2 + att*d3.
// grid (node_tiles, tower), block 480 = 32 nodes x 15 outputs
__global__ void k_post(const float* __restrict__ W_post,
                       const float* __restrict__ b_post, int l) {
    __shared__ float sA[32 * 300];
    __shared__ float sX[32 * FI];
    int nb = blockIdx.x * 32;
    int t  = blockIdx.y;
    for (int i = threadIdx.x; i < 32 * 300; i += 480) {
        int nl = i / 300, c = i - nl * 300;
        int n = nb + nl;
        sA[i] = (n < NN) ? d_aggr[(n * NT + t) * 300 + c] : 0.f;
    }
    for (int i = threadIdx.x; i < 32 * FI; i += 480) {
        int nl = i / FI, c = i - nl * FI;
        int n = nb + nl;
        sX[i] = (n < NN) ? d_x[n * FI + c] : 0.f;
    }
    __syncthreads();
    int nl = threadIdx.x / FO;
    int f  = threadIdx.x - nl * FO;
    int n = nb + nl;
    if (n >= NN) return;
    const float* W = &W_post[((size_t)l * NT + t) * 975 * FO];
    const float* xs = &sX[nl * FI];
    const float* ag = &sA[nl * 300];
    float self_ = 0.f, d1 = 0.f, d2 = 0.f, d3 = 0.f;
    #pragma unroll 5
    for (int c = 0; c < FI; c++) self_ += xs[c] * W[c * FO + f];
    #pragma unroll 4
    for (int c = 0; c < 300; c++) {
        float av = ag[c];
        d1 += av * W[(75  + c) * FO + f];
        d2 += av * W[(375 + c) * FO + f];
        d3 += av * W[(675 + c) * FO + f];
    }
    float y = b_post[(l * NT + t) * FO + f] + self_ + d1
            + d_amp[n] * d2 + d_att[n] * d3;
    d_y[n * FI + t * FO + f] = y;
}

// y2 = y @ W_lin[l] + b_lin[l]
__global__ void k_lin(const float* __restrict__ W_lin,
                      const float* __restrict__ b_lin, int l) {
    __shared__ float sy[64 * FI];
    __shared__ float sw[FI * FI];
    int nb = blockIdx.x * 64;
    for (int i = threadIdx.x; i < 64 * FI; i += 256) {
        int n = nb + i / FI;
        sy[i] = (n < NN) ? d_y[n * FI + (i % FI)] : 0.f;
    }
    for (int i = threadIdx.x; i < FI * FI; i += 256)
        sw[i] = W_lin[l * FI * FI + i];
    __syncthreads();
    for (int o = threadIdx.x; o < 64 * FI; o += 256) {
        int nl = o / FI, c = o - nl * FI;
        int n = nb + nl;
        if (n >= NN) continue;
        float acc = b_lin[l * FI + c];
        #pragma unroll 15
        for (int k = 0; k < FI; k++) acc += sy[nl * FI + k] * sw[k * FI + c];
        d_y2[n * FI + c] = acc;
    }
}

__global__ void k_bnzero() {
    if (threadIdx.x < FI) { d_bnsum[threadIdx.x] = 0.f; d_bnsq[threadIdx.x] = 0.f; }
}

__global__ void k_bnstat() {
    __shared__ float ps[FI], pq[FI];
    for (int i = threadIdx.x; i < FI; i += blockDim.x) { ps[i] = 0.f; pq[i] = 0.f; }
    __syncthreads();
    int total = NN * FI;
    for (int i = blockIdx.x * blockDim.x + threadIdx.x; i < total;
         i += gridDim.x * blockDim.x) {
        float v = d_y2[i];
        int c = i % FI;
        atomicAdd(&ps[c], v);
        atomicAdd(&pq[c], v * v);
    }
    __syncthreads();
    for (int i = threadIdx.x; i < FI; i += blockDim.x) {
        atomicAdd(&d_bnsum[i], ps[i]);
        atomicAdd(&d_bnsq[i], pq[i]);
    }
}

__global__ void k_bnfinal(const float* __restrict__ gamma,
                          const float* __restrict__ beta, int l) {
    int c = threadIdx.x;
    if (c >= FI) return;
    float mu = d_bnsum[c] / (float)NN;
    float var = fmaxf(d_bnsq[c] / (float)NN - mu * mu, 0.f);
    float sc = gamma[l * FI + c] * rsqrtf(var + 1e-5f);
    d_scale[c] = sc;
    d_shift[c] = beta[l * FI + c] - mu * sc;
}

__global__ void k_bnapply() {
    int i = blockIdx.x * blockDim.x + threadIdx.x;
    if (i >= NN * FI) return;
    int c = i % FI;
    d_x[i] = fmaxf(d_y2[i] * d_scale[c] + d_shift[c], 0.f);
}

// ---------------- readout -------------------------------------------------
__global__ void k_pool(const int* __restrict__ batch) {
    int i = blockIdx.x * blockDim.x + threadIdx.x;
    if (i >= NN * FI) return;
    int n = i / FI, c = i - n * FI;
    atomicAdd(&d_pool[batch[n] * FI + c], d_x[i]);
}

__global__ void k_mlp(const float* __restrict__ W1, const float* __restrict__ b1,
                      const float* __restrict__ W2, const float* __restrict__ b2,
                      const float* __restrict__ W3, const float* __restrict__ b3,
                      float* __restrict__ out) {
    __shared__ float sp[FI], h1[50], h2[25];
    int g = blockIdx.x;
    if (threadIdx.x < FI) sp[threadIdx.x] = d_pool[g * FI + threadIdx.x];
    __syncthreads();
    if (threadIdx.x < 50) {
        float a = b1[threadIdx.x];
        for (int c = 0; c < FI; c++) a += sp[c] * W1[c * 50 + threadIdx.x];
        h1[threadIdx.x] = fmaxf(a, 0.f);
    }
    __syncthreads();
    if (threadIdx.x < 25) {
        float a = b2[threadIdx.x];
        for (int c = 0; c < 50; c++) a += h1[c] * W2[c * 25 + threadIdx.x];
        h2[threadIdx.x] = fmaxf(a, 0.f);
    }
    __syncthreads();
    if (threadIdx.x == 0) {
        float a = b3[0];
        for (int c = 0; c < 25; c++) a += h2[c] * W3[c];
        out[g] = a;
    }
}

// ---------------- launch --------------------------------------------------
extern "C" void kernel_launch(void* const* d_in, const int* in_sizes, int n_in,
                              void* d_out, int out_size) {
    const int*   x_idx      = (const int*)d_in[0];
    const int*   edge_index = (const int*)d_in[1];
    const int*   eattr      = (const int*)d_in[2];
    const int*   batch      = (const int*)d_in[3];
    const float* node_emb   = (const float*)d_in[4];
    const float* edge_emb   = (const float*)d_in[5];
    const float* W_edge     = (const float*)d_in[6];
    const float* b_edge     = (const float*)d_in[7];
    const float* W_pre      = (const float*)d_in[8];
    const float* b_pre      = (const float*)d_in[9];
    const float* W_post     = (const float*)d_in[10];
    const float* b_post     = (const float*)d_in[11];
    const float* W_lin      = (const float*)d_in[12];
    const float* b_lin      = (const float*)d_in[13];
    const float* gamma      = (const float*)d_in[14];
    const float* beta       = (const float*)d_in[15];
    const float* W1         = (const float*)d_in[16];
    const float* b1         = (const float*)d_in[17];
    const float* W2         = (const float*)d_in[18];
    const float* b2         = (const float*)d_in[19];
    const float* W3         = (const float*)d_in[20];
    const float* b3         = (const float*)d_in[21];
    float* out = (float*)d_out;

    const int NB256_N  = (NN + 255) / 256;
    const int NB256_E  = (NE + 255) / 256;
    const int NB256_NF = (NN * FI + 255) / 256;

    // graph structure + scalers (fixed across layers)
    k_init<<<NB256_N, 256>>>();
    k_deg<<<NB256_E, 256>>>(edge_index);
    k_scan<<<1, 1024>>>();
    k_scatter<<<NB256_E, 256>>>(edge_index, eattr);
    k_logsum<<<NB256_N, 256>>>();
    k_scalers<<<NB256_N, 256>>>();
    k_gather_x<<<NB256_NF, 256>>>(x_idx, node_emb);

    for (int l = 0; l < 2; l++) {
        k_repack<<<(FI * ABW + 255) / 256, 256>>>(W_pre, l);
        k_ctab<<<100, 384>>>(edge_emb, W_edge, b_edge, W_pre, b_pre, l);
        {
            dim3 grid((ABW + BN - 1) / BN, (NN + BM - 1) / BM);
            k_gemm_ab<<<grid, 256>>>();
        }
        k_agg<<<NN, 96>>>();
        {
            dim3 grid((NN + 31) / 32, NT);
            k_post<<<grid, 480>>>(W_post, b_post, l);
        }
        k_lin<<<(NN + 63) / 64, 256>>>(W_lin, b_lin, l);
        k_bnzero<<<1, 128>>>();
        k_bnstat<<<296, 256>>>();
        k_bnfinal<<<1, 128>>>(gamma, beta, l);
        k_bnapply<<<NB256_NF, 256>>>();
    }

    k_pool<<<NB256_NF, 256>>>(batch);
    k_mlp<<<NG, 96>>>(W1, b1, W2, b2, W3, b3, out);
}

// round 10
// speedup vs baseline: 3.3853x; 3.3853x over previous
#include <cuda_runtime.h>
#include <math.h>

#define NN 20000
#define NE 320000
#define NG 200
#define FI 75
#define NT 5
#define FO 15
#define PRE 375    // towers*F_IN = 5*75
#define PREP 376   // padded (16B-aligned rows)
#define ABW 752    // dst(0..375 pad) + src(376..751 pad)
#define PN 96      // nodes per k_post2 block
#define PKC 75     // K-chunk for k_post2

// ---------------- scratch (device globals; no cudaMalloc allowed) ----------
__device__ float d_x[NN*FI];            // current node features
__device__ float d_AB[NN*ABW];          // per-node message precomp (dst part | src part)
__device__ float d_Wcat[FI*ABW];        // repacked W_pre (x-side)
__device__ float d_Ctab[100*PREP];      // per-edge-type message term (incl. b_pre)
__device__ float d_Wp[NT*PRE*48];       // repacked W_post: [t][375][48], j=f*3+g
__device__ float d_aggr[NN*NT*300];     // [N][T][mean|min|max|std]
__device__ float d_y[NN*FI];
__device__ float d_y2[NN*FI];
__device__ int   d_deg[NN];
__device__ float d_amp[NN], d_att[NN];
__device__ int   d_off[NN+1], d_cur[NN];
__device__ int   d_csr_src[NE], d_csr_type[NE];
__device__ float d_bnsum[FI], d_bnsq[FI], d_scale[FI], d_shift[FI];
__device__ float d_logsum;
__device__ float d_pool[NG*FI];

// ---------------- setup kernels -------------------------------------------
__global__ void k_init() {
    int i = blockIdx.x * blockDim.x + threadIdx.x;
    if (i < NN) d_deg[i] = 0;
    if (i < NG * FI) d_pool[i] = 0.f;
    if (i == 0) d_logsum = 0.f;
}

__global__ void k_deg(const int* __restrict__ edge_index) {
    int e = blockIdx.x * blockDim.x + threadIdx.x;
    if (e < NE) atomicAdd(&d_deg[edge_index[NE + e]], 1);
}

// single-block shuffle scan over 20000 degrees -> CSR offsets (+cursor copy)
__global__ void k_scan() {
    __shared__ int wsum[32];
    __shared__ int carry_s;
    int lane = threadIdx.x & 31, warp = threadIdx.x >> 5;
    if (threadIdx.x == 0) carry_s = 0;
    __syncthreads();
    for (int base = 0; base < NN; base += 1024) {
        int i = base + threadIdx.x;
        int v = (i < NN) ? d_deg[i] : 0;
        int x = v;
        #pragma unroll
        for (int off = 1; off < 32; off <<= 1) {
            int t = __shfl_up_sync(0xffffffffu, x, off);
            if (lane >= off) x += t;
        }
        if (lane == 31) wsum[warp] = x;
        __syncthreads();
        if (warp == 0) {
            int w = wsum[lane];
            int y = w;
            #pragma unroll
            for (int off = 1; off < 32; off <<= 1) {
                int t = __shfl_up_sync(0xffffffffu, y, off);
                if (lane >= off) y += t;
            }
            wsum[lane] = y - w;   // exclusive warp base
        }
        __syncthreads();
        int excl = x - v + wsum[warp] + carry_s;
        if (i < NN) { d_off[i] = excl; d_cur[i] = excl; }
        __syncthreads();
        if (threadIdx.x == 1023) carry_s = excl + v;
        __syncthreads();
    }
    if (threadIdx.x == 0) d_off[NN] = carry_s;
}

__global__ void k_scatter(const int* __restrict__ edge_index,
                          const int* __restrict__ eattr) {
    int e = blockIdx.x * blockDim.x + threadIdx.x;
    if (e >= NE) return;
    int dst = edge_index[NE + e];
    int p = atomicAdd(&d_cur[dst], 1);
    d_csr_src[p]  = edge_index[e];
    d_csr_type[p] = eattr[e];
}

__global__ void k_logsum() {
    __shared__ float p[256];
    int i = blockIdx.x * 256 + threadIdx.x;
    float v = (i < NN) ? logf((float)d_deg[i] + 1.f) : 0.f;
    p[threadIdx.x] = v;
    __syncthreads();
    for (int s = 128; s > 0; s >>= 1) {
        if (threadIdx.x < s) p[threadIdx.x] += p[threadIdx.x + s];
        __syncthreads();
    }
    if (threadIdx.x == 0) atomicAdd(&d_logsum, p[0]);
}

__global__ void k_scalers() {
    int i = blockIdx.x * blockDim.x + threadIdx.x;
    if (i >= NN) return;
    float avg = d_logsum / (float)NN;
    int deg = d_deg[i];
    float degc = (deg > 0) ? (float)deg : 1.f;
    float ld = logf(degc + 1.f);
    d_amp[i] = ld / avg;
    d_att[i] = avg / ld;
}

__global__ void k_gather_x(const int* __restrict__ x_idx,
                           const float* __restrict__ node_emb) {
    int i = blockIdx.x * blockDim.x + threadIdx.x;
    if (i >= NN * FI) return;
    int n = i / FI, c = i - n * FI;
    d_x[i] = node_emb[x_idx[n] * FI + c];
}

// ---------------- per-layer kernels ---------------------------------------
// repack W_pre x-side into [75][752]: cols 0..374 = dst coeffs, 376..750 = src, pads 0
__global__ void k_repack(const float* __restrict__ W_pre, int l) {
    int i = blockIdx.x * blockDim.x + threadIdx.x;
    if (i >= FI * ABW) return;
    int c = i / ABW, j = i - c * ABW;
    float v = 0.f;
    if (j < PRE) {
        int t = j / FI, f = j - t * FI;
        v = W_pre[(((size_t)l * NT + t) * 225 + c) * FI + f];
    } else if (j >= PREP && j < PREP + PRE) {
        int jj = j - PREP;
        int t = jj / FI, f = jj - t * FI;
        v = W_pre[(((size_t)l * NT + t) * 225 + FI + c) * FI + f];
    }
    d_Wcat[i] = v;
}

// repack W_post into d_Wp[t][c(375)][j(48)], j = f*3 + g.
// input row c<75: self features (only g=0 path); c>=75: aggr rows, g selects
// d1 (rows 75..374), d2 (+300), d3 (+600). Cols 45..47 zero pad.
__global__ void k_repost(const float* __restrict__ W_post, int l) {
    int i = blockIdx.x * blockDim.x + threadIdx.x;
    if (i >= NT * PRE * 48) return;
    int t = i / (PRE * 48);
    int r = (i / 48) % PRE;
    int j = i % 48;
    float v = 0.f;
    if (j < 45) {
        int f = j / 3, g = j - f * 3;
        if (r < FI) {
            if (g == 0) v = W_post[(((size_t)l * NT + t) * 975 + r) * FO + f];
        } else {
            int row = r + 300 * g;  // 75..374 / 375..674 / 675..974
            v = W_post[(((size_t)l * NT + t) * 975 + row) * FO + f];
        }
    }
    d_Wp[i] = v;
}

// per-edge-type message term: C[type][t*75+f] = (edge_emb@W_edge+b_edge)@W_pre_e + b_pre
__global__ void k_ctab(const float* __restrict__ edge_emb,
                       const float* __restrict__ W_edge,
                       const float* __restrict__ b_edge,
                       const float* __restrict__ W_pre,
                       const float* __restrict__ b_pre, int l) {
    __shared__ float se[FI];
    int t = blockIdx.x;
    if (threadIdx.x < FI) {
        float a = b_edge[l * FI + threadIdx.x];
        #pragma unroll 10
        for (int c = 0; c < 50; c++)
            a += edge_emb[t * 50 + c] * W_edge[(l * 50 + c) * FI + threadIdx.x];
        se[threadIdx.x] = a;
    }
    __syncthreads();
    int j = threadIdx.x;
    if (j < PRE) {
        int tw = j / FI, f = j - tw * FI;
        float a = b_pre[(l * NT + tw) * FI + f];
        #pragma unroll 15
        for (int c = 0; c < FI; c++)
            a += se[c] * W_pre[(((size_t)l * NT + tw) * 225 + 150 + c) * FI + f];
        d_Ctab[t * PREP + j] = a;
    } else if (j == PRE) {
        d_Ctab[t * PREP + PRE] = 0.f;   // pad
    }
}

// AB = x[NN,75] @ Wcat[75,752]
#define BM 64
#define BN 64
#define BK 25
__global__ void k_gemm_ab() {
    __shared__ float As[BM][BK];
    __shared__ float Bs[BK][BN + 1];
    int row0 = blockIdx.y * BM, col0 = blockIdx.x * BN;
    int tx = threadIdx.x & 15, ty = threadIdx.x >> 4;
    float acc[4][4] = {};
    for (int kt = 0; kt < FI; kt += BK) {
        for (int i = threadIdx.x; i < BM * BK; i += 256) {
            int r = i / BK, k = i - r * BK;
            int gr = row0 + r;
            As[r][k] = (gr < NN) ? d_x[gr * FI + kt + k] : 0.f;
        }
        for (int i = threadIdx.x; i < BK * BN; i += 256) {
            int k = i / BN, c = i - k * BN;
            int gc = col0 + c;
            Bs[k][c] = (gc < ABW) ? d_Wcat[(kt + k) * ABW + gc] : 0.f;
        }
        __syncthreads();
        #pragma unroll
        for (int k = 0; k < BK; k++) {
            float a[4], b[4];
            #pragma unroll
            for (int i = 0; i < 4; i++) a[i] = As[ty * 4 + i][k];
            #pragma unroll
            for (int j = 0; j < 4; j++) b[j] = Bs[k][tx * 4 + j];
            #pragma unroll
            for (int i = 0; i < 4; i++)
                #pragma unroll
                for (int j = 0; j < 4; j++) acc[i][j] += a[i] * b[j];
        }
        __syncthreads();
    }
    for (int i = 0; i < 4; i++) {
        int gr = row0 + ty * 4 + i;
        if (gr >= NN) continue;
        for (int j = 0; j < 4; j++) {
            int gc = col0 + tx * 4 + j;
            if (gc < ABW) d_AB[gr * ABW + gc] = acc[i][j];
        }
    }
}

// multi-aggregator reduction per node. block = node, 96 threads, float4 lanes.
// Edge loop unrolled x2 for MLP (4 independent float4 loads in flight).
__global__ __launch_bounds__(96) void k_agg() {
    int n = blockIdx.x;
    int t = threadIdx.x;
    int begin = d_off[n], end = d_off[n + 1];
    int deg = end - begin;
    if (t >= 94) return;
    const float4* AB4 = (const float4*)d_AB;
    const float4* C4  = (const float4*)d_Ctab;
    float4 a = AB4[n * (ABW / 4) + t];          // dst part
    float4 s = {0,0,0,0}, q = {0,0,0,0};
    float4 mn = { 3.4e38f, 3.4e38f, 3.4e38f, 3.4e38f};
    float4 mx = {-3.4e38f,-3.4e38f,-3.4e38f,-3.4e38f};
    int e = begin;
    for (; e + 1 < end; e += 2) {
        int src0 = d_csr_src[e],     tpe0 = d_csr_type[e];
        int src1 = d_csr_src[e + 1], tpe1 = d_csr_type[e + 1];
        float4 b0 = AB4[src0 * (ABW / 4) + (PREP / 4) + t];
        float4 c0 = C4[tpe0 * (PREP / 4) + t];
        float4 b1 = AB4[src1 * (ABW / 4) + (PREP / 4) + t];
        float4 c1 = C4[tpe1 * (PREP / 4) + t];
        float m0 = a.x + b0.x + c0.x;
        float m1 = a.y + b0.y + c0.y;
        float m2 = a.z + b0.z + c0.z;
        float m3 = a.w + b0.w + c0.w;
        s.x += m0; q.x += m0*m0; mn.x = fminf(mn.x, m0); mx.x = fmaxf(mx.x, m0);
        s.y += m1; q.y += m1*m1; mn.y = fminf(mn.y, m1); mx.y = fmaxf(mx.y, m1);
        s.z += m2; q.z += m2*m2; mn.z = fminf(mn.z, m2); mx.z = fmaxf(mx.z, m2);
        s.w += m3; q.w += m3*m3; mn.w = fminf(mn.w, m3); mx.w = fmaxf(mx.w, m3);
        float n0 = a.x + b1.x + c1.x;
        float n1 = a.y + b1.y + c1.y;
        float n2 = a.z + b1.z + c1.z;
        float n3 = a.w + b1.w + c1.w;
        s.x += n0; q.x += n0*n0; mn.x = fminf(mn.x, n0); mx.x = fmaxf(mx.x, n0);
        s.y += n1; q.y += n1*n1; mn.y = fminf(mn.y, n1); mx.y = fmaxf(mx.y, n1);
        s.z += n2; q.z += n2*n2; mn.z = fminf(mn.z, n2); mx.z = fmaxf(mx.z, n2);
        s.w += n3; q.w += n3*n3; mn.w = fminf(mn.w, n3); mx.w = fmaxf(mx.w, n3);
    }
    if (e < end) {
        int src = d_csr_src[e];
        int tpe = d_csr_type[e];
        float4 b = AB4[src * (ABW / 4) + (PREP / 4) + t];
        float4 c = C4[tpe * (PREP / 4) + t];
        float m0 = a.x + b.x + c.x;
        float m1 = a.y + b.y + c.y;
        float m2 = a.z + b.z + c.z;
        float m3 = a.w + b.w + c.w;
        s.x += m0; q.x += m0*m0; mn.x = fminf(mn.x, m0); mx.x = fmaxf(mx.x, m0);
        s.y += m1; q.y += m1*m1; mn.y = fminf(mn.y, m1); mx.y = fmaxf(mx.y, m1);
        s.z += m2; q.z += m2*m2; mn.z = fminf(mn.z, m2); mx.z = fmaxf(mx.z, m2);
        s.w += m3; q.w += m3*m3; mn.w = fminf(mn.w, m3); mx.w = fmaxf(mx.w, m3);
    }
    float invd = (deg > 0) ? 1.f / (float)deg : 1.f;
    float sa[4] = {s.x, s.y, s.z, s.w};
    float qa[4] = {q.x, q.y, q.z, q.w};
    float mna[4] = {mn.x, mn.y, mn.z, mn.w};
    float mxa[4] = {mx.x, mx.y, mx.z, mx.w};
    #pragma unroll
    for (int k = 0; k < 4; k++) {
        int f = 4 * t + k;
        if (f >= PRE) break;
        float mean = sa[k] * invd;
        float msq  = qa[k] * invd;
        float sd = sqrtf(fmaxf(msq - mean * mean, 0.f) + 1e-5f);
        float lo = (deg > 0) ? mna[k] : 0.f;
        float hi = (deg > 0) ? mxa[k] : 0.f;
        int tw = f / FI, ff = f - tw * FI;
        float* o = &d_aggr[(n * NT + tw) * 300 + ff];
        o[0]   = mean;
        o[75]  = lo;
        o[150] = hi;
        o[225] = sd;
    }
}

// post-MLP as tiled GEMM: In[n][375] = [x | aggr(t)], Wp[t][375][48] (j=f*3+g).
// grid (ceil(NN/96), towers), block 256 = 16(tx=f) x 16(ty=node group of 6).
// epilogue per thread: y = b + a_d1 + amp*a_d2 + att*a_d3 (self folded in d1).
__global__ __launch_bounds__(256) void k_post2(const float* __restrict__ b_post,
                                               int l) {
    __shared__ float sIn[PN][76];
    __shared__ float sW[PKC][48];
    int nb = blockIdx.x * PN;
    int t  = blockIdx.y;
    int tx = threadIdx.x & 15, ty = threadIdx.x >> 4;
    float acc[6][3] = {};
    for (int kc = 0; kc < 5; kc++) {
        for (int i = threadIdx.x; i < PN * PKC; i += 256) {
            int nl = i / PKC, k = i - nl * PKC;
            int n = nb + nl;
            float v = 0.f;
            if (n < NN)
                v = (kc == 0) ? d_x[n * FI + k]
                              : d_aggr[(n * NT + t) * 300 + (kc - 1) * 75 + k];
            sIn[nl][k] = v;
        }
        for (int i = threadIdx.x; i < PKC * 48; i += 256) {
            int k = i / 48, j = i - k * 48;
            sW[k][j] = d_Wp[((t * PRE) + kc * PKC + k) * 48 + j];
        }
        __syncthreads();
        #pragma unroll 5
        for (int k = 0; k < PKC; k++) {
            float w0 = sW[k][tx * 3 + 0];
            float w1 = sW[k][tx * 3 + 1];
            float w2 = sW[k][tx * 3 + 2];
            #pragma unroll
            for (int i = 0; i < 6; i++) {
                float a = sIn[ty * 6 + i][k];
                acc[i][0] += a * w0;
                acc[i][1] += a * w1;
                acc[i][2] += a * w2;
            }
        }
        __syncthreads();
    }
    if (tx < FO) {
        float b = b_post[(l * NT + t) * FO + tx];
        #pragma unroll
        for (int i = 0; i < 6; i++) {
            int n = nb + ty * 6 + i;
            if (n < NN) {
                float y = b + acc[i][0] + d_amp[n] * acc[i][1]
                            + d_att[n] * acc[i][2];
                d_y[n * FI + t * FO + tx] = y;
            }
        }
    }
}

// y2 = y @ W_lin[l] + b_lin[l]
__global__ void k_lin(const float* __restrict__ W_lin,
                      const float* __restrict__ b_lin, int l) {
    __shared__ float sy[64 * FI];
    __shared__ float sw[FI * FI];
    int nb = blockIdx.x * 64;
    for (int i = threadIdx.x; i < 64 * FI; i += 256) {
        int n = nb + i / FI;
        sy[i] = (n < NN) ? d_y[n * FI + (i % FI)] : 0.f;
    }
    for (int i = threadIdx.x; i < FI * FI; i += 256)
        sw[i] = W_lin[l * FI * FI + i];
    __syncthreads();
    for (int o = threadIdx.x; o < 64 * FI; o += 256) {
        int nl = o / FI, c = o - nl * FI;
        int n = nb + nl;
        if (n >= NN) continue;
        float acc = b_lin[l * FI + c];
        #pragma unroll 15
        for (int k = 0; k < FI; k++) acc += sy[nl * FI + k] * sw[k * FI + c];
        d_y2[n * FI + c] = acc;
    }
}

__global__ void k_bnzero() {
    if (threadIdx.x < FI) { d_bnsum[threadIdx.x] = 0.f; d_bnsq[threadIdx.x] = 0.f; }
}

__global__ void k_bnstat() {
    __shared__ float ps[FI], pq[FI];
    for (int i = threadIdx.x; i < FI; i += blockDim.x) { ps[i] = 0.f; pq[i] = 0.f; }
    __syncthreads();
    int total = NN * FI;
    for (int i = blockIdx.x * blockDim.x + threadIdx.x; i < total;
         i += gridDim.x * blockDim.x) {
        float v = d_y2[i];
        int c = i % FI;
        atomicAdd(&ps[c], v);
        atomicAdd(&pq[c], v * v);
    }
    __syncthreads();
    for (int i = threadIdx.x; i < FI; i += blockDim.x) {
        atomicAdd(&d_bnsum[i], ps[i]);
        atomicAdd(&d_bnsq[i], pq[i]);
    }
}

__global__ void k_bnfinal(const float* __restrict__ gamma,
                          const float* __restrict__ beta, int l) {
    int c = threadIdx.x;
    if (c >= FI) return;
    float mu = d_bnsum[c] / (float)NN;
    float var = fmaxf(d_bnsq[c] / (float)NN - mu * mu, 0.f);
    float sc = gamma[l * FI + c] * rsqrtf(var + 1e-5f);
    d_scale[c] = sc;
    d_shift[c] = beta[l * FI + c] - mu * sc;
}

__global__ void k_bnapply() {
    int i = blockIdx.x * blockDim.x + threadIdx.x;
    if (i >= NN * FI) return;
    int c = i % FI;
    d_x[i] = fmaxf(d_y2[i] * d_scale[c] + d_shift[c], 0.f);
}

// ---------------- readout -------------------------------------------------
__global__ void k_pool(const int* __restrict__ batch) {
    int i = blockIdx.x * blockDim.x + threadIdx.x;
    if (i >= NN * FI) return;
    int n = i / FI, c = i - n * FI;
    atomicAdd(&d_pool[batch[n] * FI + c], d_x[i]);
}

__global__ void k_mlp(const float* __restrict__ W1, const float* __restrict__ b1,
                      const float* __restrict__ W2, const float* __restrict__ b2,
                      const float* __restrict__ W3, const float* __restrict__ b3,
                      float* __restrict__ out) {
    __shared__ float sp[FI], h1[50], h2[25];
    int g = blockIdx.x;
    if (threadIdx.x < FI) sp[threadIdx.x] = d_pool[g * FI + threadIdx.x];
    __syncthreads();
    if (threadIdx.x < 50) {
        float a = b1[threadIdx.x];
        for (int c = 0; c < FI; c++) a += sp[c] * W1[c * 50 + threadIdx.x];
        h1[threadIdx.x] = fmaxf(a, 0.f);
    }
    __syncthreads();
    if (threadIdx.x < 25) {
        float a = b2[threadIdx.x];
        for (int c = 0; c < 50; c++) a += h1[c] * W2[c * 25 + threadIdx.x];
        h2[threadIdx.x] = fmaxf(a, 0.f);
    }
    __syncthreads();
    if (threadIdx.x == 0) {
        float a = b3[0];
        for (int c = 0; c < 25; c++) a += h2[c] * W3[c];
        out[g] = a;
    }
}

// ---------------- launch --------------------------------------------------
extern "C" void kernel_launch(void* const* d_in, const int* in_sizes, int n_in,
                              void* d_out, int out_size) {
    const int*   x_idx      = (const int*)d_in[0];
    const int*   edge_index = (const int*)d_in[1];
    const int*   eattr      = (const int*)d_in[2];
    const int*   batch      = (const int*)d_in[3];
    const float* node_emb   = (const float*)d_in[4];
    const float* edge_emb   = (const float*)d_in[5];
    const float* W_edge     = (const float*)d_in[6];
    const float* b_edge     = (const float*)d_in[7];
    const float* W_pre      = (const float*)d_in[8];
    const float* b_pre      = (const float*)d_in[9];
    const float* W_post     = (const float*)d_in[10];
    const float* b_post     = (const float*)d_in[11];
    const float* W_lin      = (const float*)d_in[12];
    const float* b_lin      = (const float*)d_in[13];
    const float* gamma      = (const float*)d_in[14];
    const float* beta       = (const float*)d_in[15];
    const float* W1         = (const float*)d_in[16];
    const float* b1         = (const float*)d_in[17];
    const float* W2         = (const float*)d_in[18];
    const float* b2         = (const float*)d_in[19];
    const float* W3         = (const float*)d_in[20];
    const float* b3         = (const float*)d_in[21];
    float* out = (float*)d_out;

    const int NB256_N  = (NN + 255) / 256;
    const int NB256_E  = (NE + 255) / 256;
    const int NB256_NF = (NN * FI + 255) / 256;
    const dim3 postGrid((NN + PN - 1) / PN, NT);

    // graph structure + scalers (fixed across layers)
    k_init<<<NB256_N, 256>>>();
    k_deg<<<NB256_E, 256>>>(edge_index);
    k_scan<<<1, 1024>>>();
    k_scatter<<<NB256_E, 256>>>(edge_index, eattr);
    k_logsum<<<NB256_N, 256>>>();
    k_scalers<<<NB256_N, 256>>>();
    k_gather_x<<<NB256_NF, 256>>>(x_idx, node_emb);

    for (int l = 0; l < 2; l++) {
        k_repack<<<(FI * ABW + 255) / 256, 256>>>(W_pre, l);
        k_repost<<<(NT * PRE * 48 + 255) / 256, 256>>>(W_post, l);
        k_ctab<<<100, 384>>>(edge_emb, W_edge, b_edge, W_pre, b_pre, l);
        {
            dim3 grid((ABW + BN - 1) / BN, (NN + BM - 1) / BM);
            k_gemm_ab<<<grid, 256>>>();
        }
        k_agg<<<NN, 96>>>();
        k_post2<<<postGrid, 256>>>(b_post, l);
        k_lin<<<(NN + 63) / 64, 256>>>(W_lin, b_lin, l);
        k_bnzero<<<1, 128>>>();
        k_bnstat<<<296, 256>>>();
        k_bnfinal<<<1, 128>>>(gamma, beta, l);
        k_bnapply<<<NB256_NF, 256>>>();
    }

    k_pool<<<NB256_NF, 256>>>(batch);
    k_mlp<<<NG, 96>>>(W1, b1, W2, b2, W3, b3, out);
}